// round 1
// baseline (speedup 1.0000x reference)
#include <cuda_runtime.h>
#include <math.h>

// Problem constants
#define Bn   16
#define Cc   384
#define Hh   28
#define Ww   28
#define Ll   784            // H*W
#define Ff   384
#define Ee   384
#define FFNe 1536
#define NBk  12
#define NHd  8
#define WSz  7
#define Dh   48             // F / NH
#define Mrow (Bn*Ll)        // 12544

// Scratch (device globals; allocation is forbidden)
__device__ float g_xin[Mrow * (Ee + Cc)];   // [M, 768]
__device__ float g_h  [Mrow * Ff];
__device__ float g_y  [Mrow * Ff];
__device__ float g_qkv[Mrow * 3 * Ff];
__device__ float g_o  [Mrow * Ff];
__device__ float g_mid[Mrow * FFNe];

// ---------------------------------------------------------------------------
// Build concatenated input [M, 768]: [sin Fourier embed (384) | tokens (384)]
// ---------------------------------------------------------------------------
__global__ void build_xin_k(const float* __restrict__ x,
                            const float* __restrict__ ew,   // [2, E]
                            const float* __restrict__ eb)   // [E]
{
    int idx = blockIdx.x * blockDim.x + threadIdx.x;
    if (idx >= Mrow * 768) return;
    int m = idx / 768, c = idx % 768;
    int b = m / Ll, l = m % Ll;
    float val;
    if (c < Ee) {
        // xg[l] = l / 28 (repeat), yg[l] = l % 28 (tile)
        float xn = 2.0f * (float)(l / Hh) / (float)(Ww - 1) - 1.0f;
        float yn = 2.0f * (float)(l % Hh) / (float)(Hh - 1) - 1.0f;
        val = sinf(xn * ew[c] + yn * ew[Ee + c] + eb[c]);
    } else {
        int cc = c - Ee;
        val = x[(size_t)b * Cc * Ll + (size_t)cc * Ll + l];
    }
    g_xin[idx] = val;
}

// ---------------------------------------------------------------------------
// Classic SGEMM: C = A[MxK] @ W[KxN] + bias, 128x128x8 tile, 256 thr, 8x8 uK
// Epilogues: 0=store, 1=gelu store, 2=h += alpha*(..), 3=transpose-out store
// Requires: M%128==0, N%128==0, K%8==0 (true for all call sites)
// ---------------------------------------------------------------------------
template<int EPI>
__global__ __launch_bounds__(256)
void gemm_k(const float* __restrict__ A, const float* __restrict__ W,
            const float* __restrict__ bias, float* __restrict__ C,
            int M, int N, int K, const float* __restrict__ alpha_p)
{
    const int BM = 128, BN = 128, BK = 8;
    __shared__ float As[BK][BM];
    __shared__ float Bs[BK][BN];

    int tid = threadIdx.x;
    int bx = blockIdx.x, by = blockIdx.y;

    int aRow = tid >> 1;             // 0..127
    int aC4  = (tid & 1) * 4;        // 0 or 4
    int bRow = tid >> 5;             // 0..7
    int bC4  = (tid & 31) * 4;       // 0..124

    const float* Ab = A + (size_t)(by * BM) * K;
    const float* Wb = W + (size_t)bx * BN;

    float acc[8][8];
    #pragma unroll
    for (int i = 0; i < 8; i++)
        #pragma unroll
        for (int j = 0; j < 8; j++) acc[i][j] = 0.0f;

    int ty = tid >> 4, tx = tid & 15;

    for (int k0 = 0; k0 < K; k0 += BK) {
        float4 a = *reinterpret_cast<const float4*>(Ab + (size_t)aRow * K + k0 + aC4);
        As[aC4 + 0][aRow] = a.x;
        As[aC4 + 1][aRow] = a.y;
        As[aC4 + 2][aRow] = a.z;
        As[aC4 + 3][aRow] = a.w;
        float4 bv = *reinterpret_cast<const float4*>(Wb + (size_t)(k0 + bRow) * N + bC4);
        *reinterpret_cast<float4*>(&Bs[bRow][bC4]) = bv;
        __syncthreads();

        #pragma unroll
        for (int kk = 0; kk < BK; kk++) {
            float rA[8], rB[8];
            #pragma unroll
            for (int i = 0; i < 8; i++) rA[i] = As[kk][ty * 8 + i];
            #pragma unroll
            for (int j = 0; j < 8; j++) rB[j] = Bs[kk][tx * 8 + j];
            #pragma unroll
            for (int i = 0; i < 8; i++)
                #pragma unroll
                for (int j = 0; j < 8; j++)
                    acc[i][j] = fmaf(rA[i], rB[j], acc[i][j]);
        }
        __syncthreads();
    }

    float alpha = (EPI == 2) ? *alpha_p : 0.0f;

    #pragma unroll
    for (int i = 0; i < 8; i++) {
        int row = by * BM + ty * 8 + i;
        #pragma unroll
        for (int j = 0; j < 8; j++) {
            int col = bx * BN + tx * 8 + j;
            float v = acc[i][j] + bias[col];
            if (EPI == 0) {
                C[(size_t)row * N + col] = v;
            } else if (EPI == 1) {
                // exact GELU: 0.5*x*(1+erf(x/sqrt(2)))
                C[(size_t)row * N + col] = 0.5f * v * (1.0f + erff(v * 0.7071067811865475f));
            } else if (EPI == 2) {
                C[(size_t)row * N + col] += alpha * v;
            } else { // EPI == 3: out[b][col][l] = v, row = b*L + l
                int b = row / Ll, l = row % Ll;
                C[(size_t)b * Cc * Ll + (size_t)col * Ll + l] = v;
            }
        }
    }
}

// ---------------------------------------------------------------------------
// LayerNorm over F=384: one warp per token
// ---------------------------------------------------------------------------
__global__ __launch_bounds__(256)
void ln_k(const float* __restrict__ x, const float* __restrict__ s,
          const float* __restrict__ bb, float* __restrict__ y)
{
    int gw = (blockIdx.x * blockDim.x + threadIdx.x) >> 5;
    int lane = threadIdx.x & 31;
    if (gw >= Mrow) return;
    const float* xr = x + (size_t)gw * Ff;

    float v[12];
    float sum = 0.0f;
    #pragma unroll
    for (int i = 0; i < 12; i++) { v[i] = xr[lane + i * 32]; sum += v[i]; }
    #pragma unroll
    for (int o = 16; o > 0; o >>= 1) sum += __shfl_xor_sync(0xffffffffu, sum, o);
    float mean = sum * (1.0f / 384.0f);

    float var = 0.0f;
    #pragma unroll
    for (int i = 0; i < 12; i++) { float d = v[i] - mean; var += d * d; }
    #pragma unroll
    for (int o = 16; o > 0; o >>= 1) var += __shfl_xor_sync(0xffffffffu, var, o);
    var *= (1.0f / 384.0f);
    float rstd = rsqrtf(var + 1e-5f);

    float* yr = y + (size_t)gw * Ff;
    #pragma unroll
    for (int i = 0; i < 12; i++) {
        int c = lane + i * 32;
        yr[c] = (v[i] - mean) * rstd * s[c] + bb[c];
    }
}

// ---------------------------------------------------------------------------
// Windowed attention: one block per (batch, window) = 7 tokens; warp per head
// qkv layout per token: [q(384) | k(384) | v(384)], head h at cols h*48..h*48+47
// ---------------------------------------------------------------------------
__global__ __launch_bounds__(256)
void attn_k(const float* __restrict__ qkv, float* __restrict__ o)
{
    __shared__ float sh[WSz * 1152];           // 7 tokens x 1152
    __shared__ float sc[NHd][WSz * WSz];       // per-head 7x7 scores

    int bw = blockIdx.x;          // 0 .. B*112-1 ; token range [bw*7, bw*7+7)
    int m0 = bw * WSz;
    int tid = threadIdx.x;

    const float4* src = reinterpret_cast<const float4*>(qkv + (size_t)m0 * 1152);
    float4* dst = reinterpret_cast<float4*>(sh);
    for (int i = tid; i < WSz * 1152 / 4; i += 256) dst[i] = src[i];
    __syncthreads();

    int h = tid >> 5, lane = tid & 31;
    const float scale = 0.14433756729740643f;   // 1/sqrt(48)

    for (int idx = lane; idx < WSz * WSz; idx += 32) {
        int i = idx / WSz, j = idx % WSz;
        const float* q = sh + i * 1152 + h * Dh;
        const float* k = sh + j * 1152 + Ff + h * Dh;
        float d = 0.0f;
        #pragma unroll
        for (int t = 0; t < Dh; t++) d = fmaf(q[t], k[t], d);
        sc[h][idx] = d * scale;
    }
    __syncwarp();

    if (lane < WSz) {
        float* r = sc[h] + lane * WSz;
        float mx = r[0];
        #pragma unroll
        for (int j = 1; j < WSz; j++) mx = fmaxf(mx, r[j]);
        float sum = 0.0f;
        #pragma unroll
        for (int j = 0; j < WSz; j++) { float e = expf(r[j] - mx); r[j] = e; sum += e; }
        float inv = 1.0f / sum;
        #pragma unroll
        for (int j = 0; j < WSz; j++) r[j] *= inv;
    }
    __syncwarp();

    for (int idx = lane; idx < WSz * Dh; idx += 32) {
        int i = idx / Dh, d = idx % Dh;
        float a = 0.0f;
        #pragma unroll
        for (int j = 0; j < WSz; j++)
            a = fmaf(sc[h][i * WSz + j], sh[j * 1152 + 2 * Ff + h * Dh + d], a);
        o[(size_t)(m0 + i) * Ff + h * Dh + d] = a;
    }
}

// ---------------------------------------------------------------------------
// Launch
// ---------------------------------------------------------------------------
extern "C" void kernel_launch(void* const* d_in, const int* in_sizes, int n_in,
                              void* d_out, int out_size)
{
    const float* x       = (const float*)d_in[0];
    const float* embed_w = (const float*)d_in[1];
    const float* embed_b = (const float*)d_in[2];
    const float* in_w    = (const float*)d_in[3];
    const float* in_b    = (const float*)d_in[4];
    const float* ln1_s   = (const float*)d_in[5];
    const float* ln1_b   = (const float*)d_in[6];
    const float* qkv_w   = (const float*)d_in[7];
    const float* qkv_b   = (const float*)d_in[8];
    const float* proj_w  = (const float*)d_in[9];
    const float* proj_b  = (const float*)d_in[10];
    const float* ln2_s   = (const float*)d_in[11];
    const float* ln2_b   = (const float*)d_in[12];
    const float* ffn_w1  = (const float*)d_in[13];
    const float* ffn_b1  = (const float*)d_in[14];
    const float* ffn_w2  = (const float*)d_in[15];
    const float* ffn_b2  = (const float*)d_in[16];
    const float* re_alpha= (const float*)d_in[17];
    const float* out_w   = (const float*)d_in[18];
    const float* out_b   = (const float*)d_in[19];
    float* out = (float*)d_out;

    float *xin, *h, *y, *qkv, *o, *mid;
    cudaGetSymbolAddress((void**)&xin, g_xin);
    cudaGetSymbolAddress((void**)&h,   g_h);
    cudaGetSymbolAddress((void**)&y,   g_y);
    cudaGetSymbolAddress((void**)&qkv, g_qkv);
    cudaGetSymbolAddress((void**)&o,   g_o);
    cudaGetSymbolAddress((void**)&mid, g_mid);

    const int MT = Mrow / 128;   // 98 M-tiles
    const int LN_BLOCKS = Mrow * 32 / 256;  // 1568

    build_xin_k<<<(Mrow * 768 + 255) / 256, 256>>>(x, embed_w, embed_b);

    // input projection: [M,768] @ [768,384]
    gemm_k<0><<<dim3(Ff / 128, MT), 256>>>(xin, in_w, in_b, h, Mrow, Ff, Ee + Cc, nullptr);

    for (int blk = 0; blk < NBk; blk++) {
        ln_k<<<LN_BLOCKS, 256>>>(h, ln1_s + blk * Ff, ln1_b + blk * Ff, y);

        gemm_k<0><<<dim3(3 * Ff / 128, MT), 256>>>(
            y, qkv_w + (size_t)blk * Ff * 3 * Ff, qkv_b + (size_t)blk * 3 * Ff,
            qkv, Mrow, 3 * Ff, Ff, nullptr);

        attn_k<<<Bn * (Ll / WSz), 256>>>(qkv, o);

        gemm_k<2><<<dim3(Ff / 128, MT), 256>>>(
            o, proj_w + (size_t)blk * Ff * Ff, proj_b + (size_t)blk * Ff,
            h, Mrow, Ff, Ff, re_alpha + blk);

        ln_k<<<LN_BLOCKS, 256>>>(h, ln2_s + blk * Ff, ln2_b + blk * Ff, y);

        gemm_k<1><<<dim3(FFNe / 128, MT), 256>>>(
            y, ffn_w1 + (size_t)blk * Ff * FFNe, ffn_b1 + (size_t)blk * FFNe,
            mid, Mrow, FFNe, Ff, nullptr);

        gemm_k<2><<<dim3(Ff / 128, MT), 256>>>(
            mid, ffn_w2 + (size_t)blk * FFNe * Ff, ffn_b2 + (size_t)blk * Ff,
            h, Mrow, Ff, FFNe, re_alpha + blk);
    }

    // output projection + transpose to [B, C, H, W]
    gemm_k<3><<<dim3(Ff / 128, MT), 256>>>(h, out_w, out_b, out, Mrow, Cc, Ff, nullptr);
}

// round 3
// speedup vs baseline: 2.6913x; 2.6913x over previous
#include <cuda_runtime.h>
#include <math.h>
#include <stdint.h>

// Problem constants
#define Bn   16
#define Cc   384
#define Hh   28
#define Ww   28
#define Ll   784
#define Ff   384
#define Ee   384
#define FFNe 1536
#define NBk  12
#define NHd  8
#define WSz  7
#define Dh   48
#define Mrow (Bn*Ll)        // 12544

__device__ __forceinline__ float to_tf32(float x) {
    uint32_t u;
    asm("cvt.rna.tf32.f32 %0, %1;" : "=r"(u) : "f"(x));
    return __uint_as_float(u);
}

__device__ __forceinline__ void mma_tf32(float c[4],
    uint32_t a0, uint32_t a1, uint32_t a2, uint32_t a3,
    uint32_t b0, uint32_t b1)
{
    asm volatile("mma.sync.aligned.m16n8k8.row.col.f32.tf32.tf32.f32 "
        "{%0,%1,%2,%3}, {%4,%5,%6,%7}, {%8,%9}, {%0,%1,%2,%3};"
        : "+f"(c[0]), "+f"(c[1]), "+f"(c[2]), "+f"(c[3])
        : "r"(a0), "r"(a1), "r"(a2), "r"(a3), "r"(b0), "r"(b1));
}

// ---------------------------------------------------------------------------
// Scratch
// ---------------------------------------------------------------------------
__device__ float g_xin[Mrow * (Ee + Cc)];
__device__ float g_h  [Mrow * Ff];
__device__ float g_y  [Mrow * Ff];
__device__ float g_qkv[Mrow * 3 * Ff];
__device__ float g_o  [Mrow * Ff];
__device__ float g_mid[Mrow * FFNe];

// tf32-rounded weights (same layout as originals)
#define W_IN_OFF    0
#define W_QKV_OFF   294912
#define W_PROJ_OFF  5603328
#define W_FFN1_OFF  7372800
#define W_FFN2_OFF  14450688
#define W_OUT_OFF   21528576
__device__ float g_wt[21676032];

// ---------------------------------------------------------------------------
// tf32 rounding copy (float4)
// ---------------------------------------------------------------------------
__global__ void cvt_k(const float* __restrict__ src, float* __restrict__ dst, int n4)
{
    int i = blockIdx.x * blockDim.x + threadIdx.x;
    if (i >= n4) return;
    float4 v = reinterpret_cast<const float4*>(src)[i];
    v.x = to_tf32(v.x); v.y = to_tf32(v.y); v.z = to_tf32(v.z); v.w = to_tf32(v.w);
    reinterpret_cast<float4*>(dst)[i] = v;
}

// ---------------------------------------------------------------------------
// Build concatenated input [M, 768] (tf32-rounded: feeds GEMM)
// ---------------------------------------------------------------------------
__global__ void build_xin_k(const float* __restrict__ x,
                            const float* __restrict__ ew,
                            const float* __restrict__ eb)
{
    int idx = blockIdx.x * blockDim.x + threadIdx.x;
    if (idx >= Mrow * 768) return;
    int m = idx / 768, c = idx % 768;
    int b = m / Ll, l = m % Ll;
    float val;
    if (c < Ee) {
        float xn = 2.0f * (float)(l / Hh) / (float)(Ww - 1) - 1.0f;
        float yn = 2.0f * (float)(l % Hh) / (float)(Hh - 1) - 1.0f;
        val = sinf(xn * ew[c] + yn * ew[Ee + c] + eb[c]);
    } else {
        int cc = c - Ee;
        val = x[(size_t)b * Cc * Ll + (size_t)cc * Ll + l];
    }
    g_xin[idx] = to_tf32(val);
}

// ---------------------------------------------------------------------------
// tf32 mma.sync GEMM: C[M,N] = A[M,K] @ W[K,N] + bias
// CTA tile 128x128x16, 8 warps (2x4), warp tile 64x32, m16n8k8 fragments.
// A and W must already be tf32-rounded. Bias/epilogue math in fp32.
// EPI: 0=store fp32, 1=gelu->tf32 store, 2=C += alpha*(v+bias), 3=transpose-out
// ---------------------------------------------------------------------------
template<int EPI>
__global__ __launch_bounds__(256)
void gemm_mma(const float* __restrict__ A, const float* __restrict__ W,
              const float* __restrict__ bias, float* __restrict__ C,
              int K, int N, const float* __restrict__ alpha_p)
{
    __shared__ __align__(16) float As[2][128][20];
    __shared__ __align__(16) float Bs[2][16][136];

    int tid = threadIdx.x;
    int wid = tid >> 5, lane = tid & 31;
    int tg = lane & 3, rw = lane >> 2;
    int wm = (wid & 1) * 64, wn = (wid >> 1) * 32;
    int n0 = blockIdx.x * 128, m0 = blockIdx.y * 128;

    float acc[4][4][4];
    #pragma unroll
    for (int a = 0; a < 4; a++)
        #pragma unroll
        for (int b = 0; b < 4; b++)
            #pragma unroll
            for (int c = 0; c < 4; c++) acc[a][b][c] = 0.0f;

    // prologue: tile 0 -> buf 0
    #pragma unroll
    for (int j = 0; j < 2; j++) {
        int i = tid + 256 * j;
        int r = i >> 2, c4 = i & 3;
        float4 v = *reinterpret_cast<const float4*>(A + (size_t)(m0 + r) * K + c4 * 4);
        *reinterpret_cast<float4*>(&As[0][r][c4 * 4]) = v;
        int rb = i >> 5, cb = i & 31;
        float4 w = *reinterpret_cast<const float4*>(W + (size_t)rb * N + n0 + cb * 4);
        *reinterpret_cast<float4*>(&Bs[0][rb][cb * 4]) = w;
    }

    const int T = K >> 4;
    float4 pa[2], pb[2];

    for (int t = 0; t < T; t++) {
        __syncthreads();
        int cur = t & 1;
        if (t + 1 < T) {
            int k0 = (t + 1) << 4;
            #pragma unroll
            for (int j = 0; j < 2; j++) {
                int i = tid + 256 * j;
                int r = i >> 2, c4 = i & 3;
                pa[j] = *reinterpret_cast<const float4*>(A + (size_t)(m0 + r) * K + k0 + c4 * 4);
                int rb = i >> 5, cb = i & 31;
                pb[j] = *reinterpret_cast<const float4*>(W + (size_t)(k0 + rb) * N + n0 + cb * 4);
            }
        }

        #pragma unroll
        for (int ks = 0; ks < 16; ks += 8) {
            uint32_t af[4][4], bf[4][2];
            #pragma unroll
            for (int mf = 0; mf < 4; mf++) {
                int rm = wm + mf * 16 + rw;
                af[mf][0] = __float_as_uint(As[cur][rm][ks + tg]);
                af[mf][1] = __float_as_uint(As[cur][rm + 8][ks + tg]);
                af[mf][2] = __float_as_uint(As[cur][rm][ks + tg + 4]);
                af[mf][3] = __float_as_uint(As[cur][rm + 8][ks + tg + 4]);
            }
            #pragma unroll
            for (int nf = 0; nf < 4; nf++) {
                int nn = wn + nf * 8 + rw;
                bf[nf][0] = __float_as_uint(Bs[cur][ks + tg][nn]);
                bf[nf][1] = __float_as_uint(Bs[cur][ks + tg + 4][nn]);
            }
            #pragma unroll
            for (int mf = 0; mf < 4; mf++)
                #pragma unroll
                for (int nf = 0; nf < 4; nf++)
                    mma_tf32(acc[mf][nf], af[mf][0], af[mf][1], af[mf][2], af[mf][3],
                             bf[nf][0], bf[nf][1]);
        }

        if (t + 1 < T) {
            int nxt = cur ^ 1;
            #pragma unroll
            for (int j = 0; j < 2; j++) {
                int i = tid + 256 * j;
                int r = i >> 2, c4 = i & 3;
                *reinterpret_cast<float4*>(&As[nxt][r][c4 * 4]) = pa[j];
                int rb = i >> 5, cb = i & 31;
                *reinterpret_cast<float4*>(&Bs[nxt][rb][cb * 4]) = pb[j];
            }
        }
    }

    float alpha = (EPI == 2) ? *alpha_p : 0.0f;

    #pragma unroll
    for (int mf = 0; mf < 4; mf++) {
        int r0 = m0 + wm + mf * 16 + rw;
        #pragma unroll
        for (int nf = 0; nf < 4; nf++) {
            int col = n0 + wn + nf * 8 + 2 * tg;
            float bx = bias[col], by = bias[col + 1];
            float v0 = acc[mf][nf][0] + bx, v1 = acc[mf][nf][1] + by;
            float v2 = acc[mf][nf][2] + bx, v3 = acc[mf][nf][3] + by;
            if (EPI == 0) {
                *reinterpret_cast<float2*>(C + (size_t)r0 * N + col) = make_float2(v0, v1);
                *reinterpret_cast<float2*>(C + (size_t)(r0 + 8) * N + col) = make_float2(v2, v3);
            } else if (EPI == 1) {
                v0 = 0.5f * v0 * (1.0f + erff(v0 * 0.7071067811865475f));
                v1 = 0.5f * v1 * (1.0f + erff(v1 * 0.7071067811865475f));
                v2 = 0.5f * v2 * (1.0f + erff(v2 * 0.7071067811865475f));
                v3 = 0.5f * v3 * (1.0f + erff(v3 * 0.7071067811865475f));
                *reinterpret_cast<float2*>(C + (size_t)r0 * N + col) =
                    make_float2(to_tf32(v0), to_tf32(v1));
                *reinterpret_cast<float2*>(C + (size_t)(r0 + 8) * N + col) =
                    make_float2(to_tf32(v2), to_tf32(v3));
            } else if (EPI == 2) {
                float2 h0 = *reinterpret_cast<const float2*>(C + (size_t)r0 * N + col);
                float2 h1 = *reinterpret_cast<const float2*>(C + (size_t)(r0 + 8) * N + col);
                h0.x += alpha * v0; h0.y += alpha * v1;
                h1.x += alpha * v2; h1.y += alpha * v3;
                *reinterpret_cast<float2*>(C + (size_t)r0 * N + col) = h0;
                *reinterpret_cast<float2*>(C + (size_t)(r0 + 8) * N + col) = h1;
            } else { // EPI == 3: out[b][col][l]
                int b0i = r0 / Ll, l0 = r0 % Ll;
                int b1i = (r0 + 8) / Ll, l1 = (r0 + 8) % Ll;
                C[(size_t)b0i * Cc * Ll + (size_t)col * Ll + l0] = v0;
                C[(size_t)b0i * Cc * Ll + (size_t)(col + 1) * Ll + l0] = v1;
                C[(size_t)b1i * Cc * Ll + (size_t)col * Ll + l1] = v2;
                C[(size_t)b1i * Cc * Ll + (size_t)(col + 1) * Ll + l1] = v3;
            }
        }
    }
}

// ---------------------------------------------------------------------------
// LayerNorm over F=384: one warp per token; output tf32-rounded (feeds GEMM)
// ---------------------------------------------------------------------------
__global__ __launch_bounds__(256)
void ln_k(const float* __restrict__ x, const float* __restrict__ s,
          const float* __restrict__ bb, float* __restrict__ y)
{
    int gw = (blockIdx.x * blockDim.x + threadIdx.x) >> 5;
    int lane = threadIdx.x & 31;
    if (gw >= Mrow) return;
    const float* xr = x + (size_t)gw * Ff;

    float v[12];
    float sum = 0.0f;
    #pragma unroll
    for (int i = 0; i < 12; i++) { v[i] = xr[lane + i * 32]; sum += v[i]; }
    #pragma unroll
    for (int o = 16; o > 0; o >>= 1) sum += __shfl_xor_sync(0xffffffffu, sum, o);
    float mean = sum * (1.0f / 384.0f);

    float var = 0.0f;
    #pragma unroll
    for (int i = 0; i < 12; i++) { float d = v[i] - mean; var += d * d; }
    #pragma unroll
    for (int o = 16; o > 0; o >>= 1) var += __shfl_xor_sync(0xffffffffu, var, o);
    var *= (1.0f / 384.0f);
    float rstd = rsqrtf(var + 1e-5f);

    float* yr = y + (size_t)gw * Ff;
    #pragma unroll
    for (int i = 0; i < 12; i++) {
        int c = lane + i * 32;
        yr[c] = to_tf32((v[i] - mean) * rstd * s[c] + bb[c]);
    }
}

// ---------------------------------------------------------------------------
// Windowed attention; output tf32-rounded (feeds proj GEMM)
// ---------------------------------------------------------------------------
__global__ __launch_bounds__(256)
void attn_k(const float* __restrict__ qkv, float* __restrict__ o)
{
    __shared__ float sh[WSz * 1152];
    __shared__ float sc[NHd][WSz * WSz];

    int bw = blockIdx.x;
    int m0 = bw * WSz;
    int tid = threadIdx.x;

    const float4* src = reinterpret_cast<const float4*>(qkv + (size_t)m0 * 1152);
    float4* dst = reinterpret_cast<float4*>(sh);
    for (int i = tid; i < WSz * 1152 / 4; i += 256) dst[i] = src[i];
    __syncthreads();

    int h = tid >> 5, lane = tid & 31;
    const float scale = 0.14433756729740643f;

    for (int idx = lane; idx < WSz * WSz; idx += 32) {
        int i = idx / WSz, j = idx % WSz;
        const float* q = sh + i * 1152 + h * Dh;
        const float* k = sh + j * 1152 + Ff + h * Dh;
        float d = 0.0f;
        #pragma unroll
        for (int t = 0; t < Dh; t++) d = fmaf(q[t], k[t], d);
        sc[h][idx] = d * scale;
    }
    __syncwarp();

    if (lane < WSz) {
        float* r = sc[h] + lane * WSz;
        float mx = r[0];
        #pragma unroll
        for (int j = 1; j < WSz; j++) mx = fmaxf(mx, r[j]);
        float sum = 0.0f;
        #pragma unroll
        for (int j = 0; j < WSz; j++) { float e = expf(r[j] - mx); r[j] = e; sum += e; }
        float inv = 1.0f / sum;
        #pragma unroll
        for (int j = 0; j < WSz; j++) r[j] *= inv;
    }
    __syncwarp();

    for (int idx = lane; idx < WSz * Dh; idx += 32) {
        int i = idx / Dh, d = idx % Dh;
        float a = 0.0f;
        #pragma unroll
        for (int j = 0; j < WSz; j++)
            a = fmaf(sc[h][i * WSz + j], sh[j * 1152 + 2 * Ff + h * Dh + d], a);
        o[(size_t)(m0 + i) * Ff + h * Dh + d] = to_tf32(a);
    }
}

// ---------------------------------------------------------------------------
// Launch
// ---------------------------------------------------------------------------
extern "C" void kernel_launch(void* const* d_in, const int* in_sizes, int n_in,
                              void* d_out, int out_size)
{
    const float* x       = (const float*)d_in[0];
    const float* embed_w = (const float*)d_in[1];
    const float* embed_b = (const float*)d_in[2];
    const float* in_w    = (const float*)d_in[3];
    const float* in_b    = (const float*)d_in[4];
    const float* ln1_s   = (const float*)d_in[5];
    const float* ln1_b   = (const float*)d_in[6];
    const float* qkv_w   = (const float*)d_in[7];
    const float* qkv_b   = (const float*)d_in[8];
    const float* proj_w  = (const float*)d_in[9];
    const float* proj_b  = (const float*)d_in[10];
    const float* ln2_s   = (const float*)d_in[11];
    const float* ln2_b   = (const float*)d_in[12];
    const float* ffn_w1  = (const float*)d_in[13];
    const float* ffn_b1  = (const float*)d_in[14];
    const float* ffn_w2  = (const float*)d_in[15];
    const float* ffn_b2  = (const float*)d_in[16];
    const float* re_alpha= (const float*)d_in[17];
    const float* out_w   = (const float*)d_in[18];
    const float* out_b   = (const float*)d_in[19];
    float* out = (float*)d_out;

    float *xin, *h, *y, *qkv, *o, *mid, *wt;
    cudaGetSymbolAddress((void**)&xin, g_xin);
    cudaGetSymbolAddress((void**)&h,   g_h);
    cudaGetSymbolAddress((void**)&y,   g_y);
    cudaGetSymbolAddress((void**)&qkv, g_qkv);
    cudaGetSymbolAddress((void**)&o,   g_o);
    cudaGetSymbolAddress((void**)&mid, g_mid);
    cudaGetSymbolAddress((void**)&wt,  g_wt);

    const int MT = Mrow / 128;   // 98
    const int LN_BLOCKS = Mrow * 32 / 256;

    // tf32-round all weights once (same layout, no transpose)
    cvt_k<<<(294912/4 + 255)/256, 256>>>(in_w,   wt + W_IN_OFF,   294912/4);
    cvt_k<<<(5308416/4 + 255)/256, 256>>>(qkv_w, wt + W_QKV_OFF,  5308416/4);
    cvt_k<<<(1769472/4 + 255)/256, 256>>>(proj_w,wt + W_PROJ_OFF, 1769472/4);
    cvt_k<<<(7077888/4 + 255)/256, 256>>>(ffn_w1,wt + W_FFN1_OFF, 7077888/4);
    cvt_k<<<(7077888/4 + 255)/256, 256>>>(ffn_w2,wt + W_FFN2_OFF, 7077888/4);
    cvt_k<<<(147456/4 + 255)/256, 256>>>(out_w,  wt + W_OUT_OFF,  147456/4);

    build_xin_k<<<(Mrow * 768 + 255) / 256, 256>>>(x, embed_w, embed_b);

    // input projection: [M,768] @ [768,384] -> h (fp32 residual base)
    gemm_mma<0><<<dim3(Ff / 128, MT), 256>>>(xin, wt + W_IN_OFF, in_b, h, Ee + Cc, Ff, nullptr);

    for (int blk = 0; blk < NBk; blk++) {
        ln_k<<<LN_BLOCKS, 256>>>(h, ln1_s + blk * Ff, ln1_b + blk * Ff, y);

        gemm_mma<0><<<dim3(3 * Ff / 128, MT), 256>>>(
            y, wt + W_QKV_OFF + (size_t)blk * Ff * 3 * Ff, qkv_b + (size_t)blk * 3 * Ff,
            qkv, Ff, 3 * Ff, nullptr);

        attn_k<<<Bn * (Ll / WSz), 256>>>(qkv, o);

        gemm_mma<2><<<dim3(Ff / 128, MT), 256>>>(
            o, wt + W_PROJ_OFF + (size_t)blk * Ff * Ff, proj_b + (size_t)blk * Ff,
            h, Ff, Ff, re_alpha + blk);

        ln_k<<<LN_BLOCKS, 256>>>(h, ln2_s + blk * Ff, ln2_b + blk * Ff, y);

        gemm_mma<1><<<dim3(FFNe / 128, MT), 256>>>(
            y, wt + W_FFN1_OFF + (size_t)blk * Ff * FFNe, ffn_b1 + (size_t)blk * FFNe,
            mid, Ff, FFNe, nullptr);

        gemm_mma<2><<<dim3(Ff / 128, MT), 256>>>(
            mid, wt + W_FFN2_OFF + (size_t)blk * FFNe * Ff, ffn_b2 + (size_t)blk * Ff,
            h, FFNe, Ff, re_alpha + blk);
    }

    // round h for the final GEMM's A operand
    cvt_k<<<(Mrow * Ff / 4 + 255) / 256, 256>>>(h, y, Mrow * Ff / 4);

    // output projection + transpose to [B, C, H, W]
    gemm_mma<3><<<dim3(Cc / 128, MT), 256>>>(y, wt + W_OUT_OFF, out_b, out, Ff, Cc, nullptr);
}

// round 4
// speedup vs baseline: 2.9013x; 1.0780x over previous
#include <cuda_runtime.h>
#include <math.h>
#include <stdint.h>

// Problem constants
#define Bn   16
#define Cc   384
#define Hh   28
#define Ww   28
#define Ll   784
#define Ff   384
#define Ee   384
#define FFNe 1536
#define NBk  12
#define NHd  8
#define WSz  7
#define Dh   48
#define Mrow (Bn*Ll)        // 12544

#define STAGES 4

__device__ __forceinline__ float to_tf32(float x) {
    uint32_t u;
    asm("cvt.rna.tf32.f32 %0, %1;" : "=r"(u) : "f"(x));
    return __uint_as_float(u);
}
// permute k within its 16-group: contiguous LDS.128 fragments
__device__ __forceinline__ int pk(int k) {
    return (k & ~15) | ((k & 3) << 2) | ((k >> 2) & 3);
}
__device__ __forceinline__ uint32_t smem_u32(const void* p) {
    uint32_t a;
    asm("{ .reg .u64 t; cvta.to.shared.u64 t, %1; cvt.u32.u64 %0, t; }" : "=r"(a) : "l"(p));
    return a;
}
__device__ __forceinline__ void cp16(uint32_t dst, const void* src) {
    asm volatile("cp.async.cg.shared.global [%0], [%1], 16;" :: "r"(dst), "l"(src));
}
#define CP_COMMIT() asm volatile("cp.async.commit_group;" ::: "memory")
#define CP_WAIT2()  asm volatile("cp.async.wait_group 2;" ::: "memory")

__device__ __forceinline__ void mma_tf32(float c[4],
    float a0, float a1, float a2, float a3, float b0, float b1)
{
    asm volatile("mma.sync.aligned.m16n8k8.row.col.f32.tf32.tf32.f32 "
        "{%0,%1,%2,%3}, {%4,%5,%6,%7}, {%8,%9}, {%0,%1,%2,%3};"
        : "+f"(c[0]), "+f"(c[1]), "+f"(c[2]), "+f"(c[3])
        : "r"(__float_as_uint(a0)), "r"(__float_as_uint(a1)),
          "r"(__float_as_uint(a2)), "r"(__float_as_uint(a3)),
          "r"(__float_as_uint(b0)), "r"(__float_as_uint(b1)));
}

// ---------------------------------------------------------------------------
// Scratch
// ---------------------------------------------------------------------------
__device__ float g_xin[Mrow * (Ee + Cc)];
__device__ float g_h  [Mrow * Ff];
__device__ float g_y  [Mrow * Ff];
__device__ float g_qkv[Mrow * 3 * Ff];
__device__ float g_o  [Mrow * Ff];
__device__ float g_mid[Mrow * FFNe];

// weights: tf32-rounded, transposed to [N,K], k-permuted
#define W_IN_OFF    0
#define W_QKV_OFF   294912
#define W_PROJ_OFF  5603328
#define W_FFN1_OFF  7372800
#define W_FFN2_OFF  14450688
#define W_OUT_OFF   21528576
__device__ float g_wt[21676032];

// ---------------------------------------------------------------------------
// Weight prep: src [K,N] -> dst [N, pk(K)] with tf32 rounding
// ---------------------------------------------------------------------------
__global__ void transpose_perm_k(const float* __restrict__ src, float* __restrict__ dst,
                                 int K, int N)
{
    __shared__ float t[32][33];
    int mat = blockIdx.z;
    src += (size_t)mat * K * N;
    dst += (size_t)mat * K * N;
    int n0 = blockIdx.x * 32, k0 = blockIdx.y * 32;
    int tx = threadIdx.x, ty = threadIdx.y;
    #pragma unroll
    for (int i = ty; i < 32; i += 8)
        t[i][tx] = src[(size_t)(k0 + i) * N + n0 + tx];
    __syncthreads();
    #pragma unroll
    for (int i = ty; i < 32; i += 8)
        dst[(size_t)(n0 + i) * K + pk(k0 + tx)] = to_tf32(t[tx][i]);
}

// ---------------------------------------------------------------------------
// cvt + permute: dst[m][pk(k)] = tf32(src[m][k]), row width K
// ---------------------------------------------------------------------------
__global__ void cvt_perm_k(const float* __restrict__ src, float* __restrict__ dst, int n, int K)
{
    int i = blockIdx.x * blockDim.x + threadIdx.x;
    if (i >= n) return;
    int m = i / K, k = i % K;
    dst[(size_t)m * K + pk(k)] = to_tf32(src[i]);
}

// ---------------------------------------------------------------------------
// Build concatenated input [M, 768] (tf32 + permuted: feeds GEMM A)
// ---------------------------------------------------------------------------
__global__ void build_xin_k(const float* __restrict__ x,
                            const float* __restrict__ ew,
                            const float* __restrict__ eb)
{
    int idx = blockIdx.x * blockDim.x + threadIdx.x;
    if (idx >= Mrow * 768) return;
    int m = idx / 768, c = idx % 768;
    int b = m / Ll, l = m % Ll;
    float val;
    if (c < Ee) {
        float xn = 2.0f * (float)(l / Hh) / (float)(Ww - 1) - 1.0f;
        float yn = 2.0f * (float)(l % Hh) / (float)(Hh - 1) - 1.0f;
        val = sinf(xn * ew[c] + yn * ew[Ee + c] + eb[c]);
    } else {
        int cc = c - Ee;
        val = x[(size_t)b * Cc * Ll + (size_t)cc * Ll + l];
    }
    g_xin[(size_t)m * 768 + pk(c)] = to_tf32(val);
}

// ---------------------------------------------------------------------------
// tf32 mma GEMM: C[M,N] = A[M,Kperm] @ Wt[N,Kperm]^T + bias
// CTA 128x128, k-tile 16, 4-stage cp.async pipeline, LDS.128 fragments.
// EPI: 0=store fp32, 1=gelu->tf32 permuted store, 2=C += alpha*(v+bias),
//      3=transpose-out store
// ---------------------------------------------------------------------------
template<int EPI>
__global__ __launch_bounds__(256)
void gemm_mma(const float* __restrict__ A, const float* __restrict__ Wt,
              const float* __restrict__ bias, float* __restrict__ C,
              int K, int N, const float* __restrict__ alpha_p)
{
    extern __shared__ float sm[];
    float* As = sm;                         // [STAGES][128][16]
    float* Bs = sm + STAGES * 2048;         // [STAGES][128][16]
    uint32_t as_u = smem_u32(As), bs_u = smem_u32(Bs);

    int tid = threadIdx.x;
    int wid = tid >> 5, lane = tid & 31, tg = lane & 3, rw = lane >> 2;
    int wm = (wid & 1) * 64, wn = (wid >> 1) * 32;
    int n0 = blockIdx.x * 128, m0 = blockIdx.y * 128;

    // per-thread cp.async chunk sources (row = tid>>2 and +64, 16B chunk = tid&3)
    const float* Asrc0 = A  + (size_t)(m0 + (tid >> 2)) * K + (tid & 3) * 4;
    const float* Asrc1 = A  + (size_t)(m0 + 64 + (tid >> 2)) * K + (tid & 3) * 4;
    const float* Bsrc0 = Wt + (size_t)(n0 + (tid >> 2)) * K + (tid & 3) * 4;
    const float* Bsrc1 = Wt + (size_t)(n0 + 64 + (tid >> 2)) * K + (tid & 3) * 4;
    uint32_t adst0 = as_u + tid * 16;
    uint32_t adst1 = as_u + (tid + 256) * 16;
    uint32_t bdst0 = bs_u + tid * 16;
    uint32_t bdst1 = bs_u + (tid + 256) * 16;

    float acc[4][4][4];
    #pragma unroll
    for (int a = 0; a < 4; a++)
        #pragma unroll
        for (int b = 0; b < 4; b++)
            #pragma unroll
            for (int c = 0; c < 4; c++) acc[a][b][c] = 0.0f;

    const int nt = K >> 4;

    #pragma unroll
    for (int s = 0; s < STAGES - 1; s++) {
        uint32_t so = (uint32_t)(s * 8192);
        cp16(adst0 + so, Asrc0 + s * 16);
        cp16(adst1 + so, Asrc1 + s * 16);
        cp16(bdst0 + so, Bsrc0 + s * 16);
        cp16(bdst1 + so, Bsrc1 + s * 16);
        CP_COMMIT();
    }

    for (int t = 0; t < nt; t++) {
        CP_WAIT2();
        __syncthreads();

        int tn = t + STAGES - 1;
        if (tn < nt) {
            uint32_t so = (uint32_t)((tn & (STAGES - 1)) * 8192);
            cp16(adst0 + so, Asrc0 + tn * 16);
            cp16(adst1 + so, Asrc1 + tn * 16);
            cp16(bdst0 + so, Bsrc0 + tn * 16);
            cp16(bdst1 + so, Bsrc1 + tn * 16);
        }
        CP_COMMIT();

        const float* Ab = As + (t & (STAGES - 1)) * 2048;
        const float* Bb = Bs + (t & (STAGES - 1)) * 2048;

        float4 av[4][2], bv[4];
        #pragma unroll
        for (int mf = 0; mf < 4; mf++) {
            av[mf][0] = *reinterpret_cast<const float4*>(Ab + (wm + mf * 16 + rw) * 16 + tg * 4);
            av[mf][1] = *reinterpret_cast<const float4*>(Ab + (wm + mf * 16 + rw + 8) * 16 + tg * 4);
        }
        #pragma unroll
        for (int nf = 0; nf < 4; nf++)
            bv[nf] = *reinterpret_cast<const float4*>(Bb + (wn + nf * 8 + rw) * 16 + tg * 4);

        #pragma unroll
        for (int mf = 0; mf < 4; mf++)
            #pragma unroll
            for (int nf = 0; nf < 4; nf++) {
                mma_tf32(acc[mf][nf], av[mf][0].x, av[mf][1].x, av[mf][0].y, av[mf][1].y,
                         bv[nf].x, bv[nf].y);
                mma_tf32(acc[mf][nf], av[mf][0].z, av[mf][1].z, av[mf][0].w, av[mf][1].w,
                         bv[nf].z, bv[nf].w);
            }
    }

    float alpha = (EPI == 2) ? *alpha_p : 0.0f;

    #pragma unroll
    for (int mf = 0; mf < 4; mf++) {
        int r0 = m0 + wm + mf * 16 + rw;
        #pragma unroll
        for (int nf = 0; nf < 4; nf++) {
            int col = n0 + wn + nf * 8 + 2 * tg;
            float bx = bias[col], by = bias[col + 1];
            float v0 = acc[mf][nf][0] + bx, v1 = acc[mf][nf][1] + by;
            float v2 = acc[mf][nf][2] + bx, v3 = acc[mf][nf][3] + by;
            if (EPI == 0) {
                *reinterpret_cast<float2*>(C + (size_t)r0 * N + col) = make_float2(v0, v1);
                *reinterpret_cast<float2*>(C + (size_t)(r0 + 8) * N + col) = make_float2(v2, v3);
            } else if (EPI == 1) {
                v0 = 0.5f * v0 * (1.0f + erff(v0 * 0.7071067811865475f));
                v1 = 0.5f * v1 * (1.0f + erff(v1 * 0.7071067811865475f));
                v2 = 0.5f * v2 * (1.0f + erff(v2 * 0.7071067811865475f));
                v3 = 0.5f * v3 * (1.0f + erff(v3 * 0.7071067811865475f));
                int c0 = pk(col), c1 = pk(col + 1);
                C[(size_t)r0 * N + c0] = to_tf32(v0);
                C[(size_t)r0 * N + c1] = to_tf32(v1);
                C[(size_t)(r0 + 8) * N + c0] = to_tf32(v2);
                C[(size_t)(r0 + 8) * N + c1] = to_tf32(v3);
            } else if (EPI == 2) {
                float2 h0 = *reinterpret_cast<const float2*>(C + (size_t)r0 * N + col);
                float2 h1 = *reinterpret_cast<const float2*>(C + (size_t)(r0 + 8) * N + col);
                h0.x += alpha * v0; h0.y += alpha * v1;
                h1.x += alpha * v2; h1.y += alpha * v3;
                *reinterpret_cast<float2*>(C + (size_t)r0 * N + col) = h0;
                *reinterpret_cast<float2*>(C + (size_t)(r0 + 8) * N + col) = h1;
            } else { // EPI == 3: out[b][col][l]
                int b0i = r0 / Ll, l0 = r0 % Ll;
                int b1i = (r0 + 8) / Ll, l1 = (r0 + 8) % Ll;
                C[(size_t)b0i * Cc * Ll + (size_t)col * Ll + l0] = v0;
                C[(size_t)b0i * Cc * Ll + (size_t)(col + 1) * Ll + l0] = v1;
                C[(size_t)b1i * Cc * Ll + (size_t)col * Ll + l1] = v2;
                C[(size_t)b1i * Cc * Ll + (size_t)(col + 1) * Ll + l1] = v3;
            }
        }
    }
}

// ---------------------------------------------------------------------------
// LayerNorm F=384: warp/token; output tf32 + permuted (feeds GEMM A)
// ---------------------------------------------------------------------------
__global__ __launch_bounds__(256)
void ln_k(const float* __restrict__ x, const float* __restrict__ s,
          const float* __restrict__ bb, float* __restrict__ y)
{
    int gw = (blockIdx.x * blockDim.x + threadIdx.x) >> 5;
    int lane = threadIdx.x & 31;
    if (gw >= Mrow) return;
    const float* xr = x + (size_t)gw * Ff;

    float v[12];
    float sum = 0.0f;
    #pragma unroll
    for (int i = 0; i < 12; i++) { v[i] = xr[lane + i * 32]; sum += v[i]; }
    #pragma unroll
    for (int o = 16; o > 0; o >>= 1) sum += __shfl_xor_sync(0xffffffffu, sum, o);
    float mean = sum * (1.0f / 384.0f);

    float var = 0.0f;
    #pragma unroll
    for (int i = 0; i < 12; i++) { float d = v[i] - mean; var += d * d; }
    #pragma unroll
    for (int o = 16; o > 0; o >>= 1) var += __shfl_xor_sync(0xffffffffu, var, o);
    var *= (1.0f / 384.0f);
    float rstd = rsqrtf(var + 1e-5f);

    float* yr = y + (size_t)gw * Ff;
    #pragma unroll
    for (int i = 0; i < 12; i++) {
        int c = lane + i * 32;
        yr[pk(c)] = to_tf32((v[i] - mean) * rstd * s[c] + bb[c]);
    }
}

// ---------------------------------------------------------------------------
// Windowed attention; output tf32 + permuted (feeds proj GEMM A)
// ---------------------------------------------------------------------------
__global__ __launch_bounds__(256)
void attn_k(const float* __restrict__ qkv, float* __restrict__ o)
{
    __shared__ float sh[WSz * 1152];
    __shared__ float sc[NHd][WSz * WSz];

    int bw = blockIdx.x;
    int m0 = bw * WSz;
    int tid = threadIdx.x;

    const float4* src = reinterpret_cast<const float4*>(qkv + (size_t)m0 * 1152);
    float4* dst = reinterpret_cast<float4*>(sh);
    for (int i = tid; i < WSz * 1152 / 4; i += 256) dst[i] = src[i];
    __syncthreads();

    int h = tid >> 5, lane = tid & 31;
    const float scale = 0.14433756729740643f;

    for (int idx = lane; idx < WSz * WSz; idx += 32) {
        int i = idx / WSz, j = idx % WSz;
        const float* q = sh + i * 1152 + h * Dh;
        const float* k = sh + j * 1152 + Ff + h * Dh;
        float d = 0.0f;
        #pragma unroll
        for (int t = 0; t < Dh; t++) d = fmaf(q[t], k[t], d);
        sc[h][idx] = d * scale;
    }
    __syncwarp();

    if (lane < WSz) {
        float* r = sc[h] + lane * WSz;
        float mx = r[0];
        #pragma unroll
        for (int j = 1; j < WSz; j++) mx = fmaxf(mx, r[j]);
        float sum = 0.0f;
        #pragma unroll
        for (int j = 0; j < WSz; j++) { float e = expf(r[j] - mx); r[j] = e; sum += e; }
        float inv = 1.0f / sum;
        #pragma unroll
        for (int j = 0; j < WSz; j++) r[j] *= inv;
    }
    __syncwarp();

    for (int idx = lane; idx < WSz * Dh; idx += 32) {
        int i = idx / Dh, d = idx % Dh;
        float a = 0.0f;
        #pragma unroll
        for (int j = 0; j < WSz; j++)
            a = fmaf(sc[h][i * WSz + j], sh[j * 1152 + 2 * Ff + h * Dh + d], a);
        o[(size_t)(m0 + i) * Ff + pk(h * Dh + d)] = to_tf32(a);
    }
}

// ---------------------------------------------------------------------------
// Launch
// ---------------------------------------------------------------------------
extern "C" void kernel_launch(void* const* d_in, const int* in_sizes, int n_in,
                              void* d_out, int out_size)
{
    const float* x       = (const float*)d_in[0];
    const float* embed_w = (const float*)d_in[1];
    const float* embed_b = (const float*)d_in[2];
    const float* in_w    = (const float*)d_in[3];
    const float* in_b    = (const float*)d_in[4];
    const float* ln1_s   = (const float*)d_in[5];
    const float* ln1_b   = (const float*)d_in[6];
    const float* qkv_w   = (const float*)d_in[7];
    const float* qkv_b   = (const float*)d_in[8];
    const float* proj_w  = (const float*)d_in[9];
    const float* proj_b  = (const float*)d_in[10];
    const float* ln2_s   = (const float*)d_in[11];
    const float* ln2_b   = (const float*)d_in[12];
    const float* ffn_w1  = (const float*)d_in[13];
    const float* ffn_b1  = (const float*)d_in[14];
    const float* ffn_w2  = (const float*)d_in[15];
    const float* ffn_b2  = (const float*)d_in[16];
    const float* re_alpha= (const float*)d_in[17];
    const float* out_w   = (const float*)d_in[18];
    const float* out_b   = (const float*)d_in[19];
    float* out = (float*)d_out;

    float *xin, *h, *y, *qkv, *o, *mid, *wt;
    cudaGetSymbolAddress((void**)&xin, g_xin);
    cudaGetSymbolAddress((void**)&h,   g_h);
    cudaGetSymbolAddress((void**)&y,   g_y);
    cudaGetSymbolAddress((void**)&qkv, g_qkv);
    cudaGetSymbolAddress((void**)&o,   g_o);
    cudaGetSymbolAddress((void**)&mid, g_mid);
    cudaGetSymbolAddress((void**)&wt,  g_wt);

    const int SMSZ = STAGES * 2048 * 2 * 4;   // 65536
    cudaFuncSetAttribute(gemm_mma<0>, cudaFuncAttributeMaxDynamicSharedMemorySize, SMSZ);
    cudaFuncSetAttribute(gemm_mma<1>, cudaFuncAttributeMaxDynamicSharedMemorySize, SMSZ);
    cudaFuncSetAttribute(gemm_mma<2>, cudaFuncAttributeMaxDynamicSharedMemorySize, SMSZ);
    cudaFuncSetAttribute(gemm_mma<3>, cudaFuncAttributeMaxDynamicSharedMemorySize, SMSZ);

    const int MT = Mrow / 128;   // 98
    const int LN_BLOCKS = Mrow * 32 / 256;
    dim3 tb(32, 8);

    // weight prep: transpose to [N,K], permute k, tf32-round
    transpose_perm_k<<<dim3(Ff/32,   (Ee+Cc)/32, 1),  tb>>>(in_w,   wt + W_IN_OFF,   Ee + Cc, Ff);
    transpose_perm_k<<<dim3(3*Ff/32, Ff/32,      12), tb>>>(qkv_w,  wt + W_QKV_OFF,  Ff, 3 * Ff);
    transpose_perm_k<<<dim3(Ff/32,   Ff/32,      12), tb>>>(proj_w, wt + W_PROJ_OFF, Ff, Ff);
    transpose_perm_k<<<dim3(FFNe/32, Ff/32,      12), tb>>>(ffn_w1, wt + W_FFN1_OFF, Ff, FFNe);
    transpose_perm_k<<<dim3(Ff/32,   FFNe/32,    12), tb>>>(ffn_w2, wt + W_FFN2_OFF, FFNe, Ff);
    transpose_perm_k<<<dim3(Cc/32,   Ff/32,      1),  tb>>>(out_w,  wt + W_OUT_OFF,  Ff, Cc);

    build_xin_k<<<(Mrow * 768 + 255) / 256, 256>>>(x, embed_w, embed_b);

    // input projection: [M,768] @ [768,384] -> h (fp32 residual, normal layout)
    gemm_mma<0><<<dim3(Ff / 128, MT), 256, SMSZ>>>(xin, wt + W_IN_OFF, in_b, h, Ee + Cc, Ff, nullptr);

    for (int blk = 0; blk < NBk; blk++) {
        ln_k<<<LN_BLOCKS, 256>>>(h, ln1_s + blk * Ff, ln1_b + blk * Ff, y);

        gemm_mma<0><<<dim3(3 * Ff / 128, MT), 256, SMSZ>>>(
            y, wt + W_QKV_OFF + (size_t)blk * Ff * 3 * Ff, qkv_b + (size_t)blk * 3 * Ff,
            qkv, Ff, 3 * Ff, nullptr);

        attn_k<<<Bn * (Ll / WSz), 256>>>(qkv, o);

        gemm_mma<2><<<dim3(Ff / 128, MT), 256, SMSZ>>>(
            o, wt + W_PROJ_OFF + (size_t)blk * Ff * Ff, proj_b + (size_t)blk * Ff,
            h, Ff, Ff, re_alpha + blk);

        ln_k<<<LN_BLOCKS, 256>>>(h, ln2_s + blk * Ff, ln2_b + blk * Ff, y);

        gemm_mma<1><<<dim3(FFNe / 128, MT), 256, SMSZ>>>(
            y, wt + W_FFN1_OFF + (size_t)blk * Ff * FFNe, ffn_b1 + (size_t)blk * FFNe,
            mid, Ff, FFNe, nullptr);

        gemm_mma<2><<<dim3(Ff / 128, MT), 256, SMSZ>>>(
            mid, wt + W_FFN2_OFF + (size_t)blk * FFNe * Ff, ffn_b2 + (size_t)blk * Ff,
            h, FFNe, Ff, re_alpha + blk);
    }

    // round+permute h for the final GEMM's A operand
    cvt_perm_k<<<(Mrow * Ff + 255) / 256, 256>>>(h, y, Mrow * Ff, Ff);

    // output projection + transpose to [B, C, H, W]
    gemm_mma<3><<<dim3(Cc / 128, MT), 256, SMSZ>>>(y, wt + W_OUT_OFF, out_b, out, Ff, Cc, nullptr);
}

// round 6
// speedup vs baseline: 3.9571x; 1.3639x over previous
#include <cuda_runtime.h>
#include <cuda_fp16.h>
#include <math.h>
#include <stdint.h>

// Problem constants
#define Bn   16
#define Cc   384
#define Hh   28
#define Ww   28
#define Ll   784
#define Ff   384
#define Ee   384
#define FFNe 1536
#define NBk  12
#define NHd  8
#define WSz  7
#define Dh   48
#define Mrow (Bn*Ll)        // 12544

#define STAGES 4

// fp16 k-permutation: pair p=k>>1 within 16-pair (32-k) group -> p'=((p&3)<<2)|(p>>2)
__device__ __forceinline__ int pk16(int k) {
    int p = (k >> 1) & 15;
    int pp = ((p & 3) << 2) | (p >> 2);
    return (k & ~31) | (pp << 1) | (k & 1);
}
__device__ __forceinline__ uint32_t smem_u32(const void* p) {
    uint32_t a;
    asm("{ .reg .u64 t; cvta.to.shared.u64 t, %1; cvt.u32.u64 %0, t; }" : "=r"(a) : "l"(p));
    return a;
}
__device__ __forceinline__ void cp16(uint32_t dst, const void* src) {
    asm volatile("cp.async.cg.shared.global [%0], [%1], 16;" :: "r"(dst), "l"(src));
}
#define CP_COMMIT() asm volatile("cp.async.commit_group;" ::: "memory")
#define CP_WAIT2()  asm volatile("cp.async.wait_group 2;" ::: "memory")

// m16n8k16 fp16 mma, f32 accumulate
__device__ __forceinline__ void mma_f16(float c[4],
    uint32_t a0, uint32_t a1, uint32_t a2, uint32_t a3, uint32_t b0, uint32_t b1)
{
    asm volatile("mma.sync.aligned.m16n8k16.row.col.f32.f16.f16.f32 "
        "{%0,%1,%2,%3}, {%4,%5,%6,%7}, {%8,%9}, {%0,%1,%2,%3};"
        : "+f"(c[0]), "+f"(c[1]), "+f"(c[2]), "+f"(c[3])
        : "r"(a0), "r"(a1), "r"(a2), "r"(a3), "r"(b0), "r"(b1));
}

// ---------------------------------------------------------------------------
// Scratch
// ---------------------------------------------------------------------------
__device__ __half g_xin[Mrow * (Ee + Cc)];   // fp16 permuted
__device__ float  g_h  [Mrow * Ff];          // fp32 residual
__device__ __half g_y  [Mrow * Ff];          // fp16 permuted (LN out / h-cvt)
__device__ float  g_qkv[Mrow * 3 * Ff];      // fp32 (attn input)
__device__ __half g_o  [Mrow * Ff];          // fp16 permuted (attn out)
__device__ __half g_mid[Mrow * FFNe];        // fp16 permuted (gelu out)

// weights: fp16, transposed to [N,K], k-permuted
#define W_IN_OFF    0
#define W_QKV_OFF   294912
#define W_PROJ_OFF  5603328
#define W_FFN1_OFF  7372800
#define W_FFN2_OFF  14450688
#define W_OUT_OFF   21528576
__device__ __half g_wt[21676032];

// ---------------------------------------------------------------------------
// Weight prep: src [K,N] fp32 -> dst [N, pk16(K)] fp16
// ---------------------------------------------------------------------------
__global__ void transpose_perm_k(const float* __restrict__ src, __half* __restrict__ dst,
                                 int K, int N)
{
    __shared__ float t[32][33];
    int mat = blockIdx.z;
    src += (size_t)mat * K * N;
    dst += (size_t)mat * K * N;
    int n0 = blockIdx.x * 32, k0 = blockIdx.y * 32;
    int tx = threadIdx.x, ty = threadIdx.y;
    #pragma unroll
    for (int i = ty; i < 32; i += 8)
        t[i][tx] = src[(size_t)(k0 + i) * N + n0 + tx];
    __syncthreads();
    #pragma unroll
    for (int i = ty; i < 32; i += 8)
        dst[(size_t)(n0 + i) * K + pk16(k0 + tx)] = __float2half(t[tx][i]);
}

// ---------------------------------------------------------------------------
// cvt + permute: dst[m][pk16(k)] = fp16(src[m][k])
// ---------------------------------------------------------------------------
__global__ void cvt_perm_k(const float* __restrict__ src, __half* __restrict__ dst, int n, int K)
{
    int i = blockIdx.x * blockDim.x + threadIdx.x;
    if (i >= n) return;
    int m = i / K, k = i % K;
    dst[(size_t)m * K + pk16(k)] = __float2half(src[i]);
}

// ---------------------------------------------------------------------------
// Build concatenated input [M, 768] fp16 permuted
// ---------------------------------------------------------------------------
__global__ void build_xin_k(const float* __restrict__ x,
                            const float* __restrict__ ew,
                            const float* __restrict__ eb)
{
    int idx = blockIdx.x * blockDim.x + threadIdx.x;
    if (idx >= Mrow * 768) return;
    int m = idx / 768, c = idx % 768;
    int b = m / Ll, l = m % Ll;
    float val;
    if (c < Ee) {
        float xn = 2.0f * (float)(l / Hh) / (float)(Ww - 1) - 1.0f;
        float yn = 2.0f * (float)(l % Hh) / (float)(Hh - 1) - 1.0f;
        val = sinf(xn * ew[c] + yn * ew[Ee + c] + eb[c]);
    } else {
        int cc = c - Ee;
        val = x[(size_t)b * Cc * Ll + (size_t)cc * Ll + l];
    }
    g_xin[(size_t)m * 768 + pk16(c)] = __float2half(val);
}

// ---------------------------------------------------------------------------
// fp16 mma GEMM: C[M,N] = A[M,Kperm] @ Wt[N,Kperm]^T + bias (f32 accum)
// CTA 128x128, k-tile 32, 4-stage cp.async, LDS.128 fragments.
// EPI: 0=store fp32, 1=gelu->fp16 permuted store, 2=C += alpha*(v+bias),
//      3=transpose-out store
// ---------------------------------------------------------------------------
template<int EPI>
__global__ __launch_bounds__(256)
void gemm_mma(const __half* __restrict__ A, const __half* __restrict__ Wt,
              const float* __restrict__ bias, float* __restrict__ C,
              int K, int N, const float* __restrict__ alpha_p)
{
    extern __shared__ __align__(16) __half sm[];
    __half* As = sm;                        // [STAGES][128][32] halfs (8KB/stage)
    __half* Bs = sm + STAGES * 4096;
    uint32_t as_u = smem_u32(As), bs_u = smem_u32(Bs);

    int tid = threadIdx.x;
    int wid = tid >> 5, lane = tid & 31, tg = lane & 3, rw = lane >> 2;
    int wm = (wid & 1) * 64, wn = (wid >> 1) * 32;
    int n0 = blockIdx.x * 128, m0 = blockIdx.y * 128;

    // cp.async: per thread 2 chunks of A (rows tid>>2, +64; chunk tid&3) + same for B
    const __half* Asrc0 = A  + (size_t)(m0 + (tid >> 2)) * K + (tid & 3) * 8;
    const __half* Asrc1 = A  + (size_t)(m0 + 64 + (tid >> 2)) * K + (tid & 3) * 8;
    const __half* Bsrc0 = Wt + (size_t)(n0 + (tid >> 2)) * K + (tid & 3) * 8;
    const __half* Bsrc1 = Wt + (size_t)(n0 + 64 + (tid >> 2)) * K + (tid & 3) * 8;
    uint32_t adst0 = as_u + tid * 16;
    uint32_t adst1 = as_u + tid * 16 + 4096;
    uint32_t bdst0 = bs_u + tid * 16;
    uint32_t bdst1 = bs_u + tid * 16 + 4096;

    float acc[4][4][4];
    #pragma unroll
    for (int a = 0; a < 4; a++)
        #pragma unroll
        for (int b = 0; b < 4; b++)
            #pragma unroll
            for (int c = 0; c < 4; c++) acc[a][b][c] = 0.0f;

    const int nt = K >> 5;

    #pragma unroll
    for (int s = 0; s < STAGES - 1; s++) {
        uint32_t so = (uint32_t)(s * 8192);
        cp16(adst0 + so, Asrc0 + s * 32);
        cp16(adst1 + so, Asrc1 + s * 32);
        cp16(bdst0 + so, Bsrc0 + s * 32);
        cp16(bdst1 + so, Bsrc1 + s * 32);
        CP_COMMIT();
    }

    for (int t = 0; t < nt; t++) {
        CP_WAIT2();
        __syncthreads();

        int tn = t + STAGES - 1;
        if (tn < nt) {
            uint32_t so = (uint32_t)((tn & (STAGES - 1)) * 8192);
            cp16(adst0 + so, Asrc0 + tn * 32);
            cp16(adst1 + so, Asrc1 + tn * 32);
            cp16(bdst0 + so, Bsrc0 + tn * 32);
            cp16(bdst1 + so, Bsrc1 + tn * 32);
        }
        CP_COMMIT();

        const __half* Ab = As + (t & (STAGES - 1)) * 4096;
        const __half* Bb = Bs + (t & (STAGES - 1)) * 4096;

        // one float4 per fragment row: 8 fp16 = both k-steps
        // .x=(kstep0,klo) .y=(kstep0,khi) .z=(kstep1,klo) .w=(kstep1,khi)
        uint4 av0[4], av1[4], bv[4];
        #pragma unroll
        for (int mf = 0; mf < 4; mf++) {
            av0[mf] = *reinterpret_cast<const uint4*>(Ab + (wm + mf * 16 + rw) * 32 + tg * 8);
            av1[mf] = *reinterpret_cast<const uint4*>(Ab + (wm + mf * 16 + rw + 8) * 32 + tg * 8);
        }
        #pragma unroll
        for (int nf = 0; nf < 4; nf++)
            bv[nf] = *reinterpret_cast<const uint4*>(Bb + (wn + nf * 8 + rw) * 32 + tg * 8);

        #pragma unroll
        for (int mf = 0; mf < 4; mf++)
            #pragma unroll
            for (int nf = 0; nf < 4; nf++) {
                mma_f16(acc[mf][nf], av0[mf].x, av1[mf].x, av0[mf].y, av1[mf].y,
                        bv[nf].x, bv[nf].y);
                mma_f16(acc[mf][nf], av0[mf].z, av1[mf].z, av0[mf].w, av1[mf].w,
                        bv[nf].z, bv[nf].w);
            }
    }

    float alpha = (EPI == 2) ? *alpha_p : 0.0f;

    #pragma unroll
    for (int mf = 0; mf < 4; mf++) {
        int r0 = m0 + wm + mf * 16 + rw;
        #pragma unroll
        for (int nf = 0; nf < 4; nf++) {
            int col = n0 + wn + nf * 8 + 2 * tg;
            float bx = bias[col], by = bias[col + 1];
            float v0 = acc[mf][nf][0] + bx, v1 = acc[mf][nf][1] + by;
            float v2 = acc[mf][nf][2] + bx, v3 = acc[mf][nf][3] + by;
            if (EPI == 0) {
                *reinterpret_cast<float2*>(C + (size_t)r0 * N + col) = make_float2(v0, v1);
                *reinterpret_cast<float2*>(C + (size_t)(r0 + 8) * N + col) = make_float2(v2, v3);
            } else if (EPI == 1) {
                v0 = 0.5f * v0 * (1.0f + erff(v0 * 0.7071067811865475f));
                v1 = 0.5f * v1 * (1.0f + erff(v1 * 0.7071067811865475f));
                v2 = 0.5f * v2 * (1.0f + erff(v2 * 0.7071067811865475f));
                v3 = 0.5f * v3 * (1.0f + erff(v3 * 0.7071067811865475f));
                __half* Ch = reinterpret_cast<__half*>(C);
                int c0 = pk16(col), c1 = pk16(col + 1);
                Ch[(size_t)r0 * N + c0] = __float2half(v0);
                Ch[(size_t)r0 * N + c1] = __float2half(v1);
                Ch[(size_t)(r0 + 8) * N + c0] = __float2half(v2);
                Ch[(size_t)(r0 + 8) * N + c1] = __float2half(v3);
            } else if (EPI == 2) {
                float2 h0 = *reinterpret_cast<const float2*>(C + (size_t)r0 * N + col);
                float2 h1 = *reinterpret_cast<const float2*>(C + (size_t)(r0 + 8) * N + col);
                h0.x += alpha * v0; h0.y += alpha * v1;
                h1.x += alpha * v2; h1.y += alpha * v3;
                *reinterpret_cast<float2*>(C + (size_t)r0 * N + col) = h0;
                *reinterpret_cast<float2*>(C + (size_t)(r0 + 8) * N + col) = h1;
            } else { // EPI == 3: out[b][col][l]
                int b0i = r0 / Ll, l0 = r0 % Ll;
                int b1i = (r0 + 8) / Ll, l1 = (r0 + 8) % Ll;
                C[(size_t)b0i * Cc * Ll + (size_t)col * Ll + l0] = v0;
                C[(size_t)b0i * Cc * Ll + (size_t)(col + 1) * Ll + l0] = v1;
                C[(size_t)b1i * Cc * Ll + (size_t)col * Ll + l1] = v2;
                C[(size_t)b1i * Cc * Ll + (size_t)(col + 1) * Ll + l1] = v3;
            }
        }
    }
}

// ---------------------------------------------------------------------------
// LayerNorm F=384: warp/token; output fp16 permuted
// ---------------------------------------------------------------------------
__global__ __launch_bounds__(256)
void ln_k(const float* __restrict__ x, const float* __restrict__ s,
          const float* __restrict__ bb, __half* __restrict__ y)
{
    int gw = (blockIdx.x * blockDim.x + threadIdx.x) >> 5;
    int lane = threadIdx.x & 31;
    if (gw >= Mrow) return;
    const float* xr = x + (size_t)gw * Ff;

    float v[12];
    float sum = 0.0f;
    #pragma unroll
    for (int i = 0; i < 12; i++) { v[i] = xr[lane + i * 32]; sum += v[i]; }
    #pragma unroll
    for (int o = 16; o > 0; o >>= 1) sum += __shfl_xor_sync(0xffffffffu, sum, o);
    float mean = sum * (1.0f / 384.0f);

    float var = 0.0f;
    #pragma unroll
    for (int i = 0; i < 12; i++) { float d = v[i] - mean; var += d * d; }
    #pragma unroll
    for (int o = 16; o > 0; o >>= 1) var += __shfl_xor_sync(0xffffffffu, var, o);
    var *= (1.0f / 384.0f);
    float rstd = rsqrtf(var + 1e-5f);

    __half* yr = y + (size_t)gw * Ff;
    #pragma unroll
    for (int i = 0; i < 12; i++) {
        int c = lane + i * 32;
        yr[pk16(c)] = __float2half((v[i] - mean) * rstd * s[c] + bb[c]);
    }
}

// ---------------------------------------------------------------------------
// Windowed attention; output fp16 permuted
// ---------------------------------------------------------------------------
__global__ __launch_bounds__(256)
void attn_k(const float* __restrict__ qkv, __half* __restrict__ o)
{
    __shared__ float sh[WSz * 1152];
    __shared__ float sc[NHd][WSz * WSz];

    int bw = blockIdx.x;
    int m0 = bw * WSz;
    int tid = threadIdx.x;

    const float4* src = reinterpret_cast<const float4*>(qkv + (size_t)m0 * 1152);
    float4* dst = reinterpret_cast<float4*>(sh);
    for (int i = tid; i < WSz * 1152 / 4; i += 256) dst[i] = src[i];
    __syncthreads();

    int h = tid >> 5, lane = tid & 31;
    const float scale = 0.14433756729740643f;

    for (int idx = lane; idx < WSz * WSz; idx += 32) {
        int i = idx / WSz, j = idx % WSz;
        const float* q = sh + i * 1152 + h * Dh;
        const float* k = sh + j * 1152 + Ff + h * Dh;
        float d = 0.0f;
        #pragma unroll
        for (int t = 0; t < Dh; t++) d = fmaf(q[t], k[t], d);
        sc[h][idx] = d * scale;
    }
    __syncwarp();

    if (lane < WSz) {
        float* r = sc[h] + lane * WSz;
        float mx = r[0];
        #pragma unroll
        for (int j = 1; j < WSz; j++) mx = fmaxf(mx, r[j]);
        float sum = 0.0f;
        #pragma unroll
        for (int j = 0; j < WSz; j++) { float e = expf(r[j] - mx); r[j] = e; sum += e; }
        float inv = 1.0f / sum;
        #pragma unroll
        for (int j = 0; j < WSz; j++) r[j] *= inv;
    }
    __syncwarp();

    for (int idx = lane; idx < WSz * Dh; idx += 32) {
        int i = idx / Dh, d = idx % Dh;
        float a = 0.0f;
        #pragma unroll
        for (int j = 0; j < WSz; j++)
            a = fmaf(sc[h][i * WSz + j], sh[j * 1152 + 2 * Ff + h * Dh + d], a);
        o[(size_t)(m0 + i) * Ff + pk16(h * Dh + d)] = __float2half(a);
    }
}

// ---------------------------------------------------------------------------
// Launch
// ---------------------------------------------------------------------------
extern "C" void kernel_launch(void* const* d_in, const int* in_sizes, int n_in,
                              void* d_out, int out_size)
{
    const float* x       = (const float*)d_in[0];
    const float* embed_w = (const float*)d_in[1];
    const float* embed_b = (const float*)d_in[2];
    const float* in_w    = (const float*)d_in[3];
    const float* in_b    = (const float*)d_in[4];
    const float* ln1_s   = (const float*)d_in[5];
    const float* ln1_b   = (const float*)d_in[6];
    const float* qkv_w   = (const float*)d_in[7];
    const float* qkv_b   = (const float*)d_in[8];
    const float* proj_w  = (const float*)d_in[9];
    const float* proj_b  = (const float*)d_in[10];
    const float* ln2_s   = (const float*)d_in[11];
    const float* ln2_b   = (const float*)d_in[12];
    const float* ffn_w1  = (const float*)d_in[13];
    const float* ffn_b1  = (const float*)d_in[14];
    const float* ffn_w2  = (const float*)d_in[15];
    const float* ffn_b2  = (const float*)d_in[16];
    const float* re_alpha= (const float*)d_in[17];
    const float* out_w   = (const float*)d_in[18];
    const float* out_b   = (const float*)d_in[19];
    float* out = (float*)d_out;

    __half *xin, *y, *o, *mid, *wt;
    float *h, *qkv;
    cudaGetSymbolAddress((void**)&xin, g_xin);
    cudaGetSymbolAddress((void**)&h,   g_h);
    cudaGetSymbolAddress((void**)&y,   g_y);
    cudaGetSymbolAddress((void**)&qkv, g_qkv);
    cudaGetSymbolAddress((void**)&o,   g_o);
    cudaGetSymbolAddress((void**)&mid, g_mid);
    cudaGetSymbolAddress((void**)&wt,  g_wt);

    const int SMSZ = STAGES * 8192 * 2;   // 65536 bytes
    cudaFuncSetAttribute(gemm_mma<0>, cudaFuncAttributeMaxDynamicSharedMemorySize, SMSZ);
    cudaFuncSetAttribute(gemm_mma<1>, cudaFuncAttributeMaxDynamicSharedMemorySize, SMSZ);
    cudaFuncSetAttribute(gemm_mma<2>, cudaFuncAttributeMaxDynamicSharedMemorySize, SMSZ);
    cudaFuncSetAttribute(gemm_mma<3>, cudaFuncAttributeMaxDynamicSharedMemorySize, SMSZ);

    const int MT = Mrow / 128;   // 98
    const int LN_BLOCKS = Mrow * 32 / 256;
    dim3 tb(32, 8);

    // weight prep: transpose to [N,K], permute k, fp16
    transpose_perm_k<<<dim3(Ff/32,   (Ee+Cc)/32, 1),  tb>>>(in_w,   wt + W_IN_OFF,   Ee + Cc, Ff);
    transpose_perm_k<<<dim3(3*Ff/32, Ff/32,      12), tb>>>(qkv_w,  wt + W_QKV_OFF,  Ff, 3 * Ff);
    transpose_perm_k<<<dim3(Ff/32,   Ff/32,      12), tb>>>(proj_w, wt + W_PROJ_OFF, Ff, Ff);
    transpose_perm_k<<<dim3(FFNe/32, Ff/32,      12), tb>>>(ffn_w1, wt + W_FFN1_OFF, Ff, FFNe);
    transpose_perm_k<<<dim3(Ff/32,   FFNe/32,    12), tb>>>(ffn_w2, wt + W_FFN2_OFF, FFNe, Ff);
    transpose_perm_k<<<dim3(Cc/32,   Ff/32,      1),  tb>>>(out_w,  wt + W_OUT_OFF,  Ff, Cc);

    build_xin_k<<<(Mrow * 768 + 255) / 256, 256>>>(x, embed_w, embed_b);

    // input projection: [M,768] @ [768,384] -> h (fp32 residual)
    gemm_mma<0><<<dim3(Ff / 128, MT), 256, SMSZ>>>(xin, wt + W_IN_OFF, in_b, h, Ee + Cc, Ff, nullptr);

    for (int blk = 0; blk < NBk; blk++) {
        ln_k<<<LN_BLOCKS, 256>>>(h, ln1_s + blk * Ff, ln1_b + blk * Ff, y);

        gemm_mma<0><<<dim3(3 * Ff / 128, MT), 256, SMSZ>>>(
            y, wt + W_QKV_OFF + (size_t)blk * Ff * 3 * Ff, qkv_b + (size_t)blk * 3 * Ff,
            qkv, Ff, 3 * Ff, nullptr);

        attn_k<<<Bn * (Ll / WSz), 256>>>(qkv, o);

        gemm_mma<2><<<dim3(Ff / 128, MT), 256, SMSZ>>>(
            o, wt + W_PROJ_OFF + (size_t)blk * Ff * Ff, proj_b + (size_t)blk * Ff,
            h, Ff, Ff, re_alpha + blk);

        ln_k<<<LN_BLOCKS, 256>>>(h, ln2_s + blk * Ff, ln2_b + blk * Ff, y);

        gemm_mma<1><<<dim3(FFNe / 128, MT), 256, SMSZ>>>(
            y, wt + W_FFN1_OFF + (size_t)blk * Ff * FFNe, ffn_b1 + (size_t)blk * FFNe,
            (float*)mid, Ff, FFNe, nullptr);

        gemm_mma<2><<<dim3(Ff / 128, MT), 256, SMSZ>>>(
            mid, wt + W_FFN2_OFF + (size_t)blk * FFNe * Ff, ffn_b2 + (size_t)blk * Ff,
            h, FFNe, Ff, re_alpha + blk);
    }

    // convert h -> fp16 permuted for the final GEMM's A operand
    cvt_perm_k<<<(Mrow * Ff + 255) / 256, 256>>>(h, y, Mrow * Ff, Ff);

    // output projection + transpose to [B, C, H, W]
    gemm_mma<3><<<dim3(Cc / 128, MT), 256, SMSZ>>>(y, wt + W_OUT_OFF, out_b, out, Ff, Cc, nullptr);
}